// round 5
// baseline (speedup 1.0000x reference)
#include <cuda_runtime.h>
#include <cuda_bf16.h>
#include <math.h>

// Problem sizes (fixed by the reference)
#define B_   32
#define T_   1024
#define D_   1024
#define H_   1024
#define N3_  3072
#define GCTAS 128

// ---------------- scratch (static device memory: allocation-guard legal) ---------
__device__ float g_XP[(size_t)B_ * T_ * N3_];   // x_proj [B*T, 3H]  (402 MB)
__device__ float g_UT[(size_t)N3_ * H_];        // U transposed: UT[n][k] = U[k][n]
__device__ float g_h[2][H_ * B_];               // h double buffer, layout (k>>2)*128 + b*4 + (k&3)
__device__ volatile unsigned g_flags[GCTAS];
__device__ volatile unsigned g_epoch;

// ---------------- reset: graph replays must start from clean state ---------------
__global__ void gru_reset_kernel() {
    int idx = blockIdx.x * blockDim.x + threadIdx.x;
    if (idx < H_ * B_) g_h[0][idx] = 0.0f;      // h0 = 0
    if (blockIdx.x == 0) {
        if (threadIdx.x < GCTAS) g_flags[threadIdx.x] = 0u;
        if (threadIdx.x == 0)    g_epoch = 0u;
    }
}

// ---------------- transpose U[1024][3072] -> UT[3072][1024] ----------------------
__global__ void transpose_u_kernel(const float* __restrict__ U) {
    __shared__ float tile[32][33];
    int bx = blockIdx.x * 32;   // n dimension (3072)
    int by = blockIdx.y * 32;   // k dimension (1024)
    int x = threadIdx.x;        // 0..31
    int y = threadIdx.y;        // 0..7
#pragma unroll
    for (int i = 0; i < 32; i += 8)
        tile[y + i][x] = U[(size_t)(by + y + i) * N3_ + bx + x];
    __syncthreads();
#pragma unroll
    for (int i = 0; i < 32; i += 8)
        g_UT[(size_t)(bx + y + i) * H_ + by + x] = tile[x][y + i];
}

// ---------------- x_proj SGEMM: C[32768,3072] = X[32768,1024] @ W[1024,3072] + b --
// 128x128 tile, BK=16, 256 threads, 8x8 per thread. All dims divide evenly.
__global__ __launch_bounds__(256) void xproj_gemm_kernel(
    const float* __restrict__ X, const float* __restrict__ W,
    const float* __restrict__ bias)
{
    __shared__ float As[16][128];   // transposed A tile: As[k][m]
    __shared__ float Bs[16][128];   // Bs[k][n]

    const int tid = threadIdx.x;
    const int m0 = blockIdx.y * 128;
    const int n0 = blockIdx.x * 128;
    const int tx = tid & 15;        // n-dir
    const int ty = tid >> 4;        // m-dir

    // A loads: 2 float4 per thread; rows 0..127, k-chunks {0,2}+{1,3}
    const int ar = tid >> 1;              // (tid*2)/4
    const int ac = (tid & 1) * 2;         // (tid*2)%4  in {0,2}
    // B loads: 2 float4 per thread
    const int br = tid >> 4;              // (tid*2)/32
    const int bc = (tid * 2) & 31;        // even

    float acc[8][8];
#pragma unroll
    for (int i = 0; i < 8; i++)
#pragma unroll
        for (int j = 0; j < 8; j++) acc[i][j] = 0.0f;

    for (int kt = 0; kt < D_; kt += 16) {
        // load A tile (transposed into smem)
        float4 av0 = *(const float4*)(X + (size_t)(m0 + ar) * D_ + kt + ac * 4);
        float4 av1 = *(const float4*)(X + (size_t)(m0 + ar) * D_ + kt + (ac + 1) * 4);
        As[ac * 4 + 0][ar] = av0.x; As[ac * 4 + 1][ar] = av0.y;
        As[ac * 4 + 2][ar] = av0.z; As[ac * 4 + 3][ar] = av0.w;
        As[ac * 4 + 4][ar] = av1.x; As[ac * 4 + 5][ar] = av1.y;
        As[ac * 4 + 6][ar] = av1.z; As[ac * 4 + 7][ar] = av1.w;
        // load B tile
        float4 bv0 = *(const float4*)(W + (size_t)(kt + br) * N3_ + n0 + bc * 4);
        float4 bv1 = *(const float4*)(W + (size_t)(kt + br) * N3_ + n0 + (bc + 1) * 4);
        *(float4*)&Bs[br][bc * 4]       = bv0;
        *(float4*)&Bs[br][(bc + 1) * 4] = bv1;
        __syncthreads();

#pragma unroll
        for (int kk = 0; kk < 16; kk++) {
            float a[8], b[8];
            float4 a0 = *(const float4*)&As[kk][ty * 8];
            float4 a1 = *(const float4*)&As[kk][ty * 8 + 4];
            float4 b0 = *(const float4*)&Bs[kk][tx * 8];
            float4 b1 = *(const float4*)&Bs[kk][tx * 8 + 4];
            a[0]=a0.x; a[1]=a0.y; a[2]=a0.z; a[3]=a0.w;
            a[4]=a1.x; a[5]=a1.y; a[6]=a1.z; a[7]=a1.w;
            b[0]=b0.x; b[1]=b0.y; b[2]=b0.z; b[3]=b0.w;
            b[4]=b1.x; b[5]=b1.y; b[6]=b1.z; b[7]=b1.w;
#pragma unroll
            for (int i = 0; i < 8; i++)
#pragma unroll
                for (int j = 0; j < 8; j++)
                    acc[i][j] = fmaf(a[i], b[j], acc[i][j]);
        }
        __syncthreads();
    }

    // epilogue: add input bias (bias row 0), store to g_XP
    float bj[8];
#pragma unroll
    for (int j = 0; j < 8; j++) bj[j] = bias[n0 + tx * 8 + j];
#pragma unroll
    for (int i = 0; i < 8; i++) {
        float* outp = g_XP + (size_t)(m0 + ty * 8 + i) * N3_ + n0 + tx * 8;
        float4 v0, v1;
        v0.x = acc[i][0] + bj[0]; v0.y = acc[i][1] + bj[1];
        v0.z = acc[i][2] + bj[2]; v0.w = acc[i][3] + bj[3];
        v1.x = acc[i][4] + bj[4]; v1.y = acc[i][5] + bj[5];
        v1.z = acc[i][6] + bj[6]; v1.w = acc[i][7] + bj[7];
        *(float4*)(outp)     = v0;
        *(float4*)(outp + 4) = v1;
    }
}

// ---------------- activations (accurate enough regardless of -use_fast_math) -----
__device__ __forceinline__ float sigm_f(float x) {
    x = fminf(fmaxf(x, -30.0f), 30.0f);
    return 1.0f / (1.0f + expf(-x));
}
__device__ __forceinline__ float tanh_f(float x) {
    float y = fminf(fmaxf(x, -15.0f), 15.0f);
    float e = expf(2.0f * y);
    return (e - 1.0f) / (e + 1.0f);
}

// ---------------- grid barrier (flag array + CTA0 aggregator) --------------------
__device__ __forceinline__ void grid_barrier(unsigned target) {
    __threadfence();          // every thread: publish my writes gpu-wide
    __syncthreads();          // all threads of this CTA done writing
    if (blockIdx.x == 0) {
        const unsigned tid = threadIdx.x;
        if (tid >= 1 && tid < GCTAS) {
            while (g_flags[tid] < target) { }
        }
        __syncthreads();
        if (tid == 0) {
            __threadfence();
            g_epoch = target;
        }
        __syncthreads();
    } else {
        if (threadIdx.x == 0) {
            g_flags[blockIdx.x] = target;
            while (g_epoch < target) { }
        }
        __syncthreads();
    }
    __threadfence();          // acquire-ish: make peers' h writes safe to read
}

// ---------------- persistent GRU recurrence --------------------------------------
// 128 CTAs x 256 threads (all co-resident on 148 SMs -> barrier is safe).
// CTA c owns h-indices j in [8c, 8c+8) across all 3 gates (24 U-columns).
// Warp w reduces K-range [128w, 128w+128); lane = batch b. Partials summed in smem.
__global__ __launch_bounds__(256, 1) void gru_recur_kernel(
    const float* __restrict__ bias, float* __restrict__ out, int out_size)
{
    __shared__ float part[8][24][32];   // [warp][col cc][b]

    const int tid  = threadIdx.x;
    const int warp = tid >> 5;
    const int lane = tid & 31;
    const int j0   = blockIdx.x * 8;

    // combine-phase role: jj = warp, b = lane
    const int cjj = warp;
    const int cb  = lane;
    const int cj  = j0 + cjj;
    const float brz = bias[N3_ + cj];
    const float brr = bias[N3_ + H_ + cj];
    const float brh = bias[N3_ + 2 * H_ + cj];
    const bool  tail = (out_size >= B_ * T_ * H_ + B_ * H_);

    const float* ut0 = g_UT + (size_t)(0 * H_ + j0) * H_;   // z columns
    const float* ut1 = g_UT + (size_t)(1 * H_ + j0) * H_;   // r columns
    const float* ut2 = g_UT + (size_t)(2 * H_ + j0) * H_;   // h columns
    const int kq0 = warp * 32;   // this warp's K-range / 4

    for (int t = 0; t < T_; t++) {
        const float*  hbuf  = g_h[t & 1];
        float*        hnext = g_h[(t & 1) ^ 1];
        const float4* h4    = (const float4*)hbuf;

        // prefetch combine inputs early (hidden under the GEMM)
        const float* xp = g_XP + (size_t)(cb * T_ + t) * N3_;
        float xz   = __ldcg(xp + cj);
        float xr   = __ldcg(xp + H_ + cj);
        float xh   = __ldcg(xp + 2 * H_ + cj);
        float hold = __ldcg(hbuf + (cj >> 2) * 128 + cb * 4 + (cj & 3));

        // ---- rec = h @ U (this warp's K-slice, lane = b, 24 cols) ----
        float acc[24];
#pragma unroll
        for (int c = 0; c < 24; c++) acc[c] = 0.0f;

        int k = kq0 * 4;
#pragma unroll 2
        for (int i = 0; i < 32; i++, k += 4) {
            float4 hv = __ldcg(h4 + (size_t)(kq0 + i) * 32 + lane);
            const float* uk0 = ut0 + k;
            const float* uk1 = ut1 + k;
            const float* uk2 = ut2 + k;
#pragma unroll
            for (int jj = 0; jj < 8; jj++) {
                float4 u;
                u = *(const float4*)(uk0 + jj * H_);
                acc[jj]      = fmaf(hv.x,u.x, fmaf(hv.y,u.y, fmaf(hv.z,u.z, fmaf(hv.w,u.w, acc[jj]))));
                u = *(const float4*)(uk1 + jj * H_);
                acc[8 + jj]  = fmaf(hv.x,u.x, fmaf(hv.y,u.y, fmaf(hv.z,u.z, fmaf(hv.w,u.w, acc[8 + jj]))));
                u = *(const float4*)(uk2 + jj * H_);
                acc[16 + jj] = fmaf(hv.x,u.x, fmaf(hv.y,u.y, fmaf(hv.z,u.z, fmaf(hv.w,u.w, acc[16 + jj]))));
            }
        }
#pragma unroll
        for (int c = 0; c < 24; c++) part[warp][c][lane] = acc[c];
        __syncthreads();

        // ---- reduce partials + gates + state update ----
        float rz = brz, rr = brr, rh = brh;
#pragma unroll
        for (int w = 0; w < 8; w++) {
            rz += part[w][cjj][cb];
            rr += part[w][8 + cjj][cb];
            rh += part[w][16 + cjj][cb];
        }
        float z  = sigm_f(xz + rz);
        float r  = sigm_f(xr + rr);
        float hh = tanh_f(xh + r * rh);
        float hn = z * hold + (1.0f - z) * hh;

        out[(size_t)(cb * T_ + t) * H_ + cj] = hn;                     // outputs[b][t][j]
        hnext[(cj >> 2) * 128 + cb * 4 + (cj & 3)] = hn;               // next h
        if (tail && t == T_ - 1)
            out[(size_t)B_ * T_ * H_ + cb * H_ + cj] = hn;             // h_last

        grid_barrier((unsigned)(t + 1));
    }
}

// ---------------- launch ---------------------------------------------------------
extern "C" void kernel_launch(void* const* d_in, const int* in_sizes, int n_in,
                              void* d_out, int out_size) {
    const float* X    = (const float*)d_in[0];   // [B,T,D]
    const float* Wk   = (const float*)d_in[1];   // [D,3H]
    const float* U    = (const float*)d_in[2];   // [H,3H]
    const float* bias = (const float*)d_in[3];   // [2,3H]
    float* out = (float*)d_out;

    gru_reset_kernel<<<GCTAS, 256>>>();
    transpose_u_kernel<<<dim3(N3_ / 32, H_ / 32), dim3(32, 8)>>>(U);
    xproj_gemm_kernel<<<dim3(N3_ / 128, (B_ * T_) / 128), 256>>>(X, Wk, bias);
    gru_recur_kernel<<<GCTAS, 256>>>(bias, out, out_size);
}

// round 6
// speedup vs baseline: 1.8002x; 1.8002x over previous
#include <cuda_runtime.h>
#include <cuda_bf16.h>
#include <math.h>

// Problem sizes (fixed by the reference)
#define B_   32
#define T_   1024
#define D_   1024
#define H_   1024
#define N3_  3072
#define GCTAS 128

// ---------------- scratch (static device memory: allocation-guard legal) ---------
__device__ float g_XP[(size_t)B_ * T_ * N3_];   // x_proj [B*T, 3H]  (402 MB)
__device__ float g_UT[(size_t)N3_ * H_];        // U transposed: UT[n][k] = U[k][n]
__device__ float g_h[2][H_ * B_];               // h double buffer, layout (k>>2)*128 + b*4 + (k&3)
__device__ volatile unsigned g_flags[GCTAS];
__device__ volatile unsigned g_epoch;

// ---------------- reset: graph replays must start from clean state ---------------
__global__ void gru_reset_kernel() {
    int idx = blockIdx.x * blockDim.x + threadIdx.x;
    if (idx < H_ * B_) g_h[0][idx] = 0.0f;      // h0 = 0
    if (blockIdx.x == 0) {
        if (threadIdx.x < GCTAS) g_flags[threadIdx.x] = 0u;
        if (threadIdx.x == 0)    g_epoch = 0u;
    }
}

// ---------------- transpose U[1024][3072] -> UT[3072][1024] ----------------------
__global__ void transpose_u_kernel(const float* __restrict__ U) {
    __shared__ float tile[32][33];
    int bx = blockIdx.x * 32;   // n dimension (3072)
    int by = blockIdx.y * 32;   // k dimension (1024)
    int x = threadIdx.x;        // 0..31
    int y = threadIdx.y;        // 0..7
#pragma unroll
    for (int i = 0; i < 32; i += 8)
        tile[y + i][x] = U[(size_t)(by + y + i) * N3_ + bx + x];
    __syncthreads();
#pragma unroll
    for (int i = 0; i < 32; i += 8)
        g_UT[(size_t)(bx + y + i) * H_ + by + x] = tile[x][y + i];
}

// ---------------- x_proj SGEMM: C[32768,3072] = X[32768,1024] @ W[1024,3072] + b --
// 128x128 tile, BK=16, 256 threads, 8x8 per thread. Near fp32 FFMA roofline.
__global__ __launch_bounds__(256) void xproj_gemm_kernel(
    const float* __restrict__ X, const float* __restrict__ W,
    const float* __restrict__ bias)
{
    __shared__ float As[16][128];   // transposed A tile: As[k][m]
    __shared__ float Bs[16][128];   // Bs[k][n]

    const int tid = threadIdx.x;
    const int m0 = blockIdx.y * 128;
    const int n0 = blockIdx.x * 128;
    const int tx = tid & 15;        // n-dir
    const int ty = tid >> 4;        // m-dir

    const int ar = tid >> 1;
    const int ac = (tid & 1) * 2;
    const int br = tid >> 4;
    const int bc = (tid * 2) & 31;

    float acc[8][8];
#pragma unroll
    for (int i = 0; i < 8; i++)
#pragma unroll
        for (int j = 0; j < 8; j++) acc[i][j] = 0.0f;

    for (int kt = 0; kt < D_; kt += 16) {
        float4 av0 = *(const float4*)(X + (size_t)(m0 + ar) * D_ + kt + ac * 4);
        float4 av1 = *(const float4*)(X + (size_t)(m0 + ar) * D_ + kt + (ac + 1) * 4);
        As[ac * 4 + 0][ar] = av0.x; As[ac * 4 + 1][ar] = av0.y;
        As[ac * 4 + 2][ar] = av0.z; As[ac * 4 + 3][ar] = av0.w;
        As[ac * 4 + 4][ar] = av1.x; As[ac * 4 + 5][ar] = av1.y;
        As[ac * 4 + 6][ar] = av1.z; As[ac * 4 + 7][ar] = av1.w;
        float4 bv0 = *(const float4*)(W + (size_t)(kt + br) * N3_ + n0 + bc * 4);
        float4 bv1 = *(const float4*)(W + (size_t)(kt + br) * N3_ + n0 + (bc + 1) * 4);
        *(float4*)&Bs[br][bc * 4]       = bv0;
        *(float4*)&Bs[br][(bc + 1) * 4] = bv1;
        __syncthreads();

#pragma unroll
        for (int kk = 0; kk < 16; kk++) {
            float a[8], b[8];
            float4 a0 = *(const float4*)&As[kk][ty * 8];
            float4 a1 = *(const float4*)&As[kk][ty * 8 + 4];
            float4 b0 = *(const float4*)&Bs[kk][tx * 8];
            float4 b1 = *(const float4*)&Bs[kk][tx * 8 + 4];
            a[0]=a0.x; a[1]=a0.y; a[2]=a0.z; a[3]=a0.w;
            a[4]=a1.x; a[5]=a1.y; a[6]=a1.z; a[7]=a1.w;
            b[0]=b0.x; b[1]=b0.y; b[2]=b0.z; b[3]=b0.w;
            b[4]=b1.x; b[5]=b1.y; b[6]=b1.z; b[7]=b1.w;
#pragma unroll
            for (int i = 0; i < 8; i++)
#pragma unroll
                for (int j = 0; j < 8; j++)
                    acc[i][j] = fmaf(a[i], b[j], acc[i][j]);
        }
        __syncthreads();
    }

    float bj[8];
#pragma unroll
    for (int j = 0; j < 8; j++) bj[j] = bias[n0 + tx * 8 + j];
#pragma unroll
    for (int i = 0; i < 8; i++) {
        float* outp = g_XP + (size_t)(m0 + ty * 8 + i) * N3_ + n0 + tx * 8;
        float4 v0, v1;
        v0.x = acc[i][0] + bj[0]; v0.y = acc[i][1] + bj[1];
        v0.z = acc[i][2] + bj[2]; v0.w = acc[i][3] + bj[3];
        v1.x = acc[i][4] + bj[4]; v1.y = acc[i][5] + bj[5];
        v1.z = acc[i][6] + bj[6]; v1.w = acc[i][7] + bj[7];
        *(float4*)(outp)     = v0;
        *(float4*)(outp + 4) = v1;
    }
}

// ---------------- activations ----------------------------------------------------
__device__ __forceinline__ float sigm_f(float x) {
    x = fminf(fmaxf(x, -30.0f), 30.0f);
    return 1.0f / (1.0f + expf(-x));
}
__device__ __forceinline__ float tanh_f(float x) {
    float y = fminf(fmaxf(x, -15.0f), 15.0f);
    float e = expf(2.0f * y);
    return (e - 1.0f) / (e + 1.0f);
}

// ---------------- grid barrier (flag array + CTA0 aggregator) --------------------
__device__ __forceinline__ void grid_barrier(unsigned target) {
    __threadfence();
    __syncthreads();
    if (blockIdx.x == 0) {
        const unsigned tid = threadIdx.x;
        if (tid >= 1 && tid < GCTAS) {
            while (g_flags[tid] < target) { }
        }
        __syncthreads();
        if (tid == 0) {
            __threadfence();
            g_epoch = target;
        }
        __syncthreads();
    } else {
        if (threadIdx.x == 0) {
            g_flags[blockIdx.x] = target;
            while (g_epoch < target) { }
        }
        __syncthreads();
    }
    __threadfence();
}

// ---------------- persistent GRU recurrence --------------------------------------
// 128 CTAs x 512 threads (16 warps). CTA c owns h-indices j in [8c, 8c+8)
// for all 3 gates (24 U-columns, cached in SMEM for the whole kernel).
// Warp w reduces K-range [64w, 64w+64); lane = batch b.
#define NW 16
#define PPAD 33
__global__ __launch_bounds__(512, 1) void gru_recur_kernel(
    const float* __restrict__ bias, float* __restrict__ out, int out_size)
{
    extern __shared__ float smem[];
    float* Us   = smem;                 // [24][1024]  (98,304 B)
    float* part = smem + 24 * 1024;     // [NW][24][PPAD] (50,688 B)

    const int tid  = threadIdx.x;
    const int warp = tid >> 5;
    const int lane = tid & 31;
    const int j0   = blockIdx.x * 8;

    // ---- fill SMEM U cache: 24 columns (3 gates x 8 j), contiguous k -----------
    {
        const float4* src0 = (const float4*)(g_UT + (size_t)(0 * H_ + j0) * H_);
        const float4* src1 = (const float4*)(g_UT + (size_t)(1 * H_ + j0) * H_);
        const float4* src2 = (const float4*)(g_UT + (size_t)(2 * H_ + j0) * H_);
        float4* dst = (float4*)Us;
        const int q = 8 * (H_ / 4);   // float4 count per gate block (2048)
        for (int i = tid; i < q; i += 512) {
            dst[i]         = src0[i];
            dst[q + i]     = src1[i];
            dst[2 * q + i] = src2[i];
        }
    }
    __syncthreads();

    // combine-phase role (threads 0..255): coalesced 32B output sectors
    const int cjj = lane & 7;                  // j within 8
    const int cb  = warp * 4 + (lane >> 3);    // batch
    const int cj  = j0 + cjj;
    const float brz = bias[N3_ + cj];
    const float brr = bias[N3_ + H_ + cj];
    const float brh = bias[N3_ + 2 * H_ + cj];
    const bool  tail = (out_size >= B_ * T_ * H_ + B_ * H_);
    const bool  comb = (tid < 256);

    const int kq0 = warp * 16;   // this warp's K-range in float4 groups (64 k's)

    for (int t = 0; t < T_; t++) {
        const float*  hbuf  = g_h[t & 1];
        float*        hnext = g_h[(t & 1) ^ 1];
        const float4* h4    = (const float4*)hbuf;

        // prefetch combine inputs early (hidden under the GEMM)
        float xz = 0.f, xr = 0.f, xh = 0.f, hold = 0.f;
        if (comb) {
            const float* xp = g_XP + (size_t)(cb * T_ + t) * N3_;
            xz   = __ldcg(xp + cj);
            xr   = __ldcg(xp + H_ + cj);
            xh   = __ldcg(xp + 2 * H_ + cj);
            hold = __ldcg(hbuf + (cj >> 2) * 128 + cb * 4 + (cj & 3));
        }

        // ---- rec = h @ U (this warp's 64-k slice, lane = b, 24 cols) ----
        float acc[24];
#pragma unroll
        for (int c = 0; c < 24; c++) acc[c] = 0.0f;

        // depth-2 prefetch of h vectors (L2-resident; ldcg avoids stale L1)
        float4 hp0 = __ldcg(h4 + (size_t)(kq0 + 0) * 32 + lane);
        float4 hp1 = __ldcg(h4 + (size_t)(kq0 + 1) * 32 + lane);
#pragma unroll 4
        for (int i = 0; i < 16; i++) {
            float4 hv = hp0;
            hp0 = hp1;
            if (i + 2 < 16)
                hp1 = __ldcg(h4 + (size_t)(kq0 + i + 2) * 32 + lane);
            const int k = (kq0 + i) * 4;
#pragma unroll
            for (int c = 0; c < 24; c++) {
                float4 u = *(const float4*)&Us[c * H_ + k];
                acc[c] = fmaf(hv.x, u.x, fmaf(hv.y, u.y,
                         fmaf(hv.z, u.z, fmaf(hv.w, u.w, acc[c]))));
            }
        }
#pragma unroll
        for (int c = 0; c < 24; c++)
            part[(warp * 24 + c) * PPAD + lane] = acc[c];
        __syncthreads();

        // ---- reduce partials + gates + state update (threads 0..255) ----
        if (comb) {
            float rz = brz, rr = brr, rh = brh;
#pragma unroll
            for (int w = 0; w < NW; w++) {
                rz += part[(w * 24 + cjj) * PPAD + cb];
                rr += part[(w * 24 + 8 + cjj) * PPAD + cb];
                rh += part[(w * 24 + 16 + cjj) * PPAD + cb];
            }
            float z  = sigm_f(xz + rz);
            float r  = sigm_f(xr + rr);
            float hh = tanh_f(xh + r * rh);
            float hn = z * hold + (1.0f - z) * hh;

            out[(size_t)(cb * T_ + t) * H_ + cj] = hn;            // outputs[b][t][j]
            hnext[(cj >> 2) * 128 + cb * 4 + (cj & 3)] = hn;      // next h
            if (tail && t == T_ - 1)
                out[(size_t)B_ * T_ * H_ + cb * H_ + cj] = hn;    // h_last
        }

        grid_barrier((unsigned)(t + 1));
    }
}

// ---------------- launch ---------------------------------------------------------
extern "C" void kernel_launch(void* const* d_in, const int* in_sizes, int n_in,
                              void* d_out, int out_size) {
    const float* X    = (const float*)d_in[0];   // [B,T,D]
    const float* Wk   = (const float*)d_in[1];   // [D,3H]
    const float* U    = (const float*)d_in[2];   // [H,3H]
    const float* bias = (const float*)d_in[3];   // [2,3H]
    float* out = (float*)d_out;

    const int smem_bytes = (24 * 1024 + NW * 24 * PPAD) * sizeof(float); // 148,992
    cudaFuncSetAttribute(gru_recur_kernel,
                         cudaFuncAttributeMaxDynamicSharedMemorySize, smem_bytes);

    gru_reset_kernel<<<GCTAS, 256>>>();
    transpose_u_kernel<<<dim3(N3_ / 32, H_ / 32), dim3(32, 8)>>>(U);
    xproj_gemm_kernel<<<dim3(N3_ / 128, (B_ * T_) / 128), 256>>>(X, Wk, bias);
    gru_recur_kernel<<<GCTAS, 512, smem_bytes>>>(bias, out, out_size);
}